// round 9
// baseline (speedup 1.0000x reference)
#include <cuda_runtime.h>
#include <cstdint>
#include <cstddef>

// Problem constants
#define Bb 64
#define Nt 577
#define Cc 768
#define Hh 12
#define SCv 0.125f
#define SPLITS 4
#define CHUNK 145       // ceil(577/4)
#define G 6             // tokens per group in k_attn

// dynamic smem layout for k_attn (float offsets)
#define XB_OFF 0
#define PL_OFF (4*G*Cc)              // 18432
#define WSM_OFF (PL_OFF + G*12*12)   // 19296
#define OBS_OFF (WSM_OFF + 2*G*16)   // 19488
#define DSM_OFF (OBS_OFF + 16)       // 19504
#define SM_FLOATS (DSM_OFF + G*12)   // 19576
#define SM_BYTES (SM_FLOATS * 4)     // 78304

// ---------------- scratch (device globals; no allocation) ----------------
__device__ __align__(16) float g_qpart[12][Bb][Cc];            // q partial sums (kc,b,j)
__device__ __align__(16) float g_t[Bb][Hh][Cc];                // SCALE * (q . Wk)
__device__ float            g_ob[Bb][Hh];                      // SCALE * (q . bk)
__device__ __align__(16) float g_pu[SPLITS][Bb][Hh][Cc];       // partial sum_n w*x
__device__ float            g_pd[SPLITS][Bb][Hh];              // partial sum_n w
__device__ __align__(16) float g_clsp[12][Bb][Cc];             // cls partials
__device__ __align__(16) float g_outp[12][Bb][Cc];             // proj partials

// ---------------- helpers ----------------
typedef unsigned long long ull;
__device__ __forceinline__ void fma2(ull &d, ull a, ull b) {
    asm("fma.rn.f32x2 %0, %1, %2, %0;" : "+l"(d) : "l"(a), "l"(b));
}
__device__ __forceinline__ float hadd2(ull a) {
    unsigned int lo, hi;
    asm("mov.b64 {%0,%1}, %2;" : "=r"(lo), "=r"(hi) : "l"(a));
    return __uint_as_float(lo) + __uint_as_float(hi);
}
__device__ __forceinline__ void cpa16(void* dst_smem, const void* src) {
    unsigned int d = (unsigned int)__cvta_generic_to_shared(dst_smem);
    asm volatile("cp.async.cg.shared.global [%0], [%1], 16;" :: "r"(d), "l"(src));
}

// ---------------- A1: q partials (k-split GEMM), 512 threads ----------------
__global__ void __launch_bounds__(512) k_qpart(const float* __restrict__ x,
                                               const float* __restrict__ qkv_w) {
    int jc = blockIdx.x, kc = blockIdx.y;
    __shared__ float xs[64][65];
    __shared__ float ws[64][65];
    int tid = threadIdx.x;
#pragma unroll
    for (int rr = 0; rr < 2; rr++) {
        int i = tid + rr * 512;
        int r = i >> 4, c4 = (i & 15) * 4;
        float4 xv = *(const float4*)&x[(size_t)r * Nt * Cc + kc * 64 + c4];
        xs[r][c4] = xv.x; xs[r][c4 + 1] = xv.y; xs[r][c4 + 2] = xv.z; xs[r][c4 + 3] = xv.w;
        float4 wv = *(const float4*)&qkv_w[(size_t)(jc * 64 + r) * Cc + kc * 64 + c4];
        ws[r][c4] = wv.x; ws[r][c4 + 1] = wv.y; ws[r][c4 + 2] = wv.z; ws[r][c4 + 3] = wv.w;
    }
    __syncthreads();
    int ty = tid >> 4, tx = tid & 15;     // 32 x 16
    float acc[2][4] = {};
#pragma unroll 8
    for (int d = 0; d < 64; d++) {
        float a0 = xs[ty * 2 + 0][d], a1 = xs[ty * 2 + 1][d];
        float b0 = ws[tx * 4 + 0][d], b1 = ws[tx * 4 + 1][d];
        float b2 = ws[tx * 4 + 2][d], b3 = ws[tx * 4 + 3][d];
        acc[0][0] += a0 * b0; acc[0][1] += a0 * b1; acc[0][2] += a0 * b2; acc[0][3] += a0 * b3;
        acc[1][0] += a1 * b0; acc[1][1] += a1 * b1; acc[1][2] += a1 * b2; acc[1][3] += a1 * b3;
    }
#pragma unroll
    for (int i = 0; i < 2; i++) {
        float4 v = make_float4(acc[i][0], acc[i][1], acc[i][2], acc[i][3]);
        *(float4*)&g_qpart[kc][ty * 2 + i][jc * 64 + tx * 4] = v;
    }
}

// ---------------- A2: t = SCALE*(q.Wk); ob  (q combined in-block), 512 thr ----------------
__global__ void __launch_bounds__(512) k_t(const float* __restrict__ qkv_w,
                                           const float* __restrict__ qkv_b) {
    int h = blockIdx.x, cc2 = blockIdx.y;
    __shared__ float qs[64][65];
    __shared__ float wk[64][65];
    int tid = threadIdx.x;
#pragma unroll
    for (int rr = 0; rr < 2; rr++) {
        int i = tid + rr * 512;
        int r = i >> 4, c4 = (i & 15) * 4;
        float4 s = *(const float4*)&qkv_b[h * 64 + c4];
#pragma unroll
        for (int kc = 0; kc < 12; kc++) {
            float4 p = *(const float4*)&g_qpart[kc][r][h * 64 + c4];
            s.x += p.x; s.y += p.y; s.z += p.z; s.w += p.w;
        }
        qs[r][c4] = s.x; qs[r][c4 + 1] = s.y; qs[r][c4 + 2] = s.z; qs[r][c4 + 3] = s.w;
        float4 wv = *(const float4*)&qkv_w[(size_t)(Cc + h * 64 + r) * Cc + cc2 * 64 + c4];
        wk[r][c4] = wv.x; wk[r][c4 + 1] = wv.y; wk[r][c4 + 2] = wv.z; wk[r][c4 + 3] = wv.w;
    }
    __syncthreads();
    int ty = tid >> 4, tx = tid & 15;
    float acc[2][4] = {};
#pragma unroll 8
    for (int d = 0; d < 64; d++) {
        float a0 = qs[ty * 2 + 0][d], a1 = qs[ty * 2 + 1][d];
        float b0 = wk[d][tx * 4 + 0], b1 = wk[d][tx * 4 + 1];
        float b2 = wk[d][tx * 4 + 2], b3 = wk[d][tx * 4 + 3];
        acc[0][0] += a0 * b0; acc[0][1] += a0 * b1; acc[0][2] += a0 * b2; acc[0][3] += a0 * b3;
        acc[1][0] += a1 * b0; acc[1][1] += a1 * b1; acc[1][2] += a1 * b2; acc[1][3] += a1 * b3;
    }
#pragma unroll
    for (int i = 0; i < 2; i++) {
        float4 v = make_float4(SCv * acc[i][0], SCv * acc[i][1], SCv * acc[i][2], SCv * acc[i][3]);
        *(float4*)&g_t[ty * 2 + i][h][cc2 * 64 + tx * 4] = v;
    }
    if (cc2 == 0 && tid < 64) {
        float ssum = 0.f;
#pragma unroll 8
        for (int d = 0; d < 64; d++) ssum += qs[tid][d] * qkv_b[Cc + h * 64 + d];
        g_ob[tid][h] = SCv * ssum;
    }
}

// ---------------- B: main fused streaming kernel (pipelined R3 bodies) ----------------
// grid (64 b, 4 split), 384 thr, dynamic smem.
__global__ void __launch_bounds__(384, 2) k_attn(const float* __restrict__ x,
                                                 float* __restrict__ out) {
    extern __shared__ float sm[];
    float (*xb)[G][Cc]  = (float(*)[G][Cc])(sm + XB_OFF);     // [4][G][Cc]
    float (*pl)[12][12] = (float(*)[12][12])(sm + PL_OFF);    // [G][12][12]
    float (*wsm)[G][16] = (float(*)[G][16])(sm + WSM_OFF);    // [2][G][16]
    float *obs = sm + OBS_OFF;
    float *dsm = sm + DSM_OFF;

    int b = blockIdx.x, sp = blockIdx.y;
    int n0 = sp * CHUNK;
    int n1 = n0 + CHUNK; if (n1 > Nt) n1 = Nt;
    int ng = (n1 - n0 + G - 1) / G;
    int tid = threadIdx.x;
    int w = tid >> 5, l = tid & 31;
    int g3 = l >> 3;           // lane group 0..3 -> heads 3*g3..3*g3+2
    int q = l & 7;             // lane in group

    int c1 = w * 64 + q * 8;
    ull t1[3][4];
#pragma unroll
    for (int i = 0; i < 3; i++) {
        ulonglong2 p0 = *(const ulonglong2*)&g_t[b][g3 * 3 + i][c1];
        ulonglong2 p1 = *(const ulonglong2*)&g_t[b][g3 * 3 + i][c1 + 4];
        t1[i][0] = p0.x; t1[i][1] = p0.y; t1[i][2] = p1.x; t1[i][3] = p1.y;
    }
    if (tid < 12) obs[tid] = g_ob[b][tid];

    int c2 = w * 64 + l * 2;
    float2 ua[12];
#pragma unroll
    for (int h = 0; h < 12; h++) ua[h] = make_float2(0.f, 0.f);
    float dp = 0.f;

    const float* xrow = x + (size_t)b * Nt * Cc;

    // --- group loader (always commits) ---
#define LOADGROUP(g) do {                                              \
        int nb_ = n0 + (g) * G;                                        \
        _Pragma("unroll")                                              \
        for (int r_ = 0; r_ < 3; r_++) {                               \
            int i_ = tid + r_ * 384;                                   \
            int j_ = i_ / 192, off_ = (i_ % 192) * 4;                  \
            int n_ = nb_ + j_;                                         \
            if (n_ < n1) cpa16(&xb[(g) & 3][j_][off_],                 \
                               xrow + (size_t)n_ * Cc + off_);         \
        }                                                              \
        asm volatile("cp.async.commit_group;");                        \
    } while (0)

    // --- phase1: logits of group g into pl ---
#define PHASE1(g) do {                                                 \
        int nb_ = n0 + (g) * G;                                        \
        _Pragma("unroll")                                              \
        for (int j_ = 0; j_ < G; j_++) {                               \
            int n_ = nb_ + j_;                                         \
            if (n_ >= n1) break;                                       \
            ulonglong2 xp0_ = *(const ulonglong2*)&xb[(g) & 3][j_][c1];\
            ulonglong2 xp1_ = *(const ulonglong2*)&xb[(g) & 3][j_][c1 + 4];\
            ull xv0_ = xp0_.x, xv1_ = xp0_.y, xv2_ = xp1_.x, xv3_ = xp1_.y;\
            float s_[3];                                               \
            _Pragma("unroll")                                          \
            for (int i_ = 0; i_ < 3; i_++) {                           \
                ull a_ = 0ull;                                         \
                fma2(a_, xv0_, t1[i_][0]); fma2(a_, xv1_, t1[i_][1]);  \
                fma2(a_, xv2_, t1[i_][2]); fma2(a_, xv3_, t1[i_][3]);  \
                float sv_ = hadd2(a_);                                 \
                sv_ += __shfl_xor_sync(0xffffffffu, sv_, 4, 8);        \
                sv_ += __shfl_xor_sync(0xffffffffu, sv_, 2, 8);        \
                sv_ += __shfl_xor_sync(0xffffffffu, sv_, 1, 8);        \
                s_[i_] = sv_;                                          \
            }                                                          \
            if (q < 3) pl[j_][w][g3 * 3 + q] = s_[q];                  \
        }                                                              \
    } while (0)

    // --- combine: 72 threads, group g -> wsm[(g)&1] ---
#define COMBINE(g) do {                                                \
        if (tid < G * 12) {                                            \
            int gg_ = tid / 12, h_ = tid % 12;                         \
            int n_ = n0 + (g) * G + gg_;                               \
            float s_ = 0.f;                                            \
            _Pragma("unroll")                                          \
            for (int ww_ = 0; ww_ < 12; ww_++) s_ += pl[gg_][ww_][h_]; \
            float wv_ = (n_ < n1) ? __expf(s_ + obs[h_]) : 0.f;        \
            dp += wv_;                                                 \
            wsm[(g) & 1][gg_][h_] = wv_;                               \
        }                                                              \
    } while (0)

    // prologue: prefetch groups 0..2, then logits+weights for group 0
    LOADGROUP(0); LOADGROUP(1); LOADGROUP(2);
    asm volatile("cp.async.wait_group 2;");
    __syncthreads();
    PHASE1(0);
    __syncthreads();
    COMBINE(0);

    for (int gi = 0; gi < ng; gi++) {
        asm volatile("cp.async.wait_group 1;");
        __syncthreads();                               // S1: xb[gi+1] ready; pl free; wsm[gi&1] ready
        if (gi + 3 < ng) { LOADGROUP(gi + 3); }
        else { asm volatile("cp.async.commit_group;"); }
        if (gi + 1 < ng) PHASE1(gi + 1);
        __syncthreads();                               // S2: pl(gi+1) published
        if (gi + 1 < ng) COMBINE(gi + 1);
        // phase2(gi): accumulate + copy out (overlaps combine)
        {
            int nbase = n0 + gi * G;
#pragma unroll
            for (int j = 0; j < G; j++) {
                int n = nbase + j;
                if (n >= n1) break;
                float4 wA = *(const float4*)&wsm[gi & 1][j][0];
                float4 wB = *(const float4*)&wsm[gi & 1][j][4];
                float4 wC = *(const float4*)&wsm[gi & 1][j][8];
                float2 xv = *(const float2*)&xb[gi & 3][j][c2];
                ua[0].x = fmaf(wA.x, xv.x, ua[0].x);  ua[0].y = fmaf(wA.x, xv.y, ua[0].y);
                ua[1].x = fmaf(wA.y, xv.x, ua[1].x);  ua[1].y = fmaf(wA.y, xv.y, ua[1].y);
                ua[2].x = fmaf(wA.z, xv.x, ua[2].x);  ua[2].y = fmaf(wA.z, xv.y, ua[2].y);
                ua[3].x = fmaf(wA.w, xv.x, ua[3].x);  ua[3].y = fmaf(wA.w, xv.y, ua[3].y);
                ua[4].x = fmaf(wB.x, xv.x, ua[4].x);  ua[4].y = fmaf(wB.x, xv.y, ua[4].y);
                ua[5].x = fmaf(wB.y, xv.x, ua[5].x);  ua[5].y = fmaf(wB.y, xv.y, ua[5].y);
                ua[6].x = fmaf(wB.z, xv.x, ua[6].x);  ua[6].y = fmaf(wB.z, xv.y, ua[6].y);
                ua[7].x = fmaf(wB.w, xv.x, ua[7].x);  ua[7].y = fmaf(wB.w, xv.y, ua[7].y);
                ua[8].x = fmaf(wC.x, xv.x, ua[8].x);  ua[8].y = fmaf(wC.x, xv.y, ua[8].y);
                ua[9].x = fmaf(wC.y, xv.x, ua[9].x);  ua[9].y = fmaf(wC.y, xv.y, ua[9].y);
                ua[10].x = fmaf(wC.z, xv.x, ua[10].x); ua[10].y = fmaf(wC.z, xv.y, ua[10].y);
                ua[11].x = fmaf(wC.w, xv.x, ua[11].x); ua[11].y = fmaf(wC.w, xv.y, ua[11].y);
                if (n > 0)
                    *(float2*)&out[((size_t)b * Nt + n) * Cc + c2] = xv;
            }
        }
    }

    // epilogue: store split partials
#pragma unroll
    for (int h = 0; h < 12; h++)
        *(float2*)&g_pu[sp][b][h][c2] = ua[h];
    if (tid < G * 12) dsm[tid] = dp;
    __syncthreads();
    if (tid < 12) {
        float s = 0.f;
#pragma unroll
        for (int gg = 0; gg < G; gg++) s += dsm[gg * 12 + tid];
        g_pd[sp][b][tid] = s;
    }
#undef LOADGROUP
#undef PHASE1
#undef COMBINE
}

// ---------------- C1: cls partials (fused split-combine + normalize), 512 thr ----------------
__global__ void __launch_bounds__(512) k_cls(const float* __restrict__ qkv_w) {
    int h = blockIdx.x, kc = blockIdx.y;
    __shared__ float us[64][65];
    __shared__ float wv[64][65];
    __shared__ float dsh[64];
    int tid = threadIdx.x;
    if (tid < 64) {
        float s = 0.f;
#pragma unroll
        for (int sp = 0; sp < SPLITS; sp++) s += g_pd[sp][tid][h];
        dsh[tid] = 1.f / s;
    }
    __syncthreads();
#pragma unroll
    for (int rr = 0; rr < 2; rr++) {
        int i = tid + rr * 512;
        int r = i >> 4, c4 = (i & 15) * 4;
        float4 acc = make_float4(0.f, 0.f, 0.f, 0.f);
#pragma unroll
        for (int sp = 0; sp < SPLITS; sp++) {
            float4 p = *(const float4*)&g_pu[sp][r][h][kc * 64 + c4];
            acc.x += p.x; acc.y += p.y; acc.z += p.z; acc.w += p.w;
        }
        float inv = dsh[r];
        us[r][c4] = acc.x * inv; us[r][c4 + 1] = acc.y * inv;
        us[r][c4 + 2] = acc.z * inv; us[r][c4 + 3] = acc.w * inv;
        float4 wvv = *(const float4*)&qkv_w[(size_t)(2 * Cc + h * 64 + r) * Cc + kc * 64 + c4];
        wv[r][c4] = wvv.x; wv[r][c4 + 1] = wvv.y; wv[r][c4 + 2] = wvv.z; wv[r][c4 + 3] = wvv.w;
    }
    __syncthreads();
    int ty = tid >> 4, tx = tid & 15;
    float acc[2][4] = {};
#pragma unroll 8
    for (int c = 0; c < 64; c++) {
        float a0 = us[ty * 2 + 0][c], a1 = us[ty * 2 + 1][c];
        float b0 = wv[tx * 4 + 0][c], b1 = wv[tx * 4 + 1][c];
        float b2 = wv[tx * 4 + 2][c], b3 = wv[tx * 4 + 3][c];
        acc[0][0] += a0 * b0; acc[0][1] += a0 * b1; acc[0][2] += a0 * b2; acc[0][3] += a0 * b3;
        acc[1][0] += a1 * b0; acc[1][1] += a1 * b1; acc[1][2] += a1 * b2; acc[1][3] += a1 * b3;
    }
#pragma unroll
    for (int i = 0; i < 2; i++) {
        float4 v = make_float4(acc[i][0], acc[i][1], acc[i][2], acc[i][3]);
        *(float4*)&g_clsp[kc][ty * 2 + i][h * 64 + tx * 4] = v;
    }
}

// ---------------- C2: proj partials, 512 thr ----------------
__global__ void __launch_bounds__(512) k_proj(const float* __restrict__ qkv_b,
                                              const float* __restrict__ proj_w) {
    int jc = blockIdx.x, kc = blockIdx.y;
    __shared__ float cs[64][65];
    __shared__ float pw[64][65];
    int tid = threadIdx.x;
#pragma unroll
    for (int rr = 0; rr < 2; rr++) {
        int i = tid + rr * 512;
        int r = i >> 4, c4 = (i & 15) * 4;
        float4 s = *(const float4*)&qkv_b[2 * Cc + kc * 64 + c4];
#pragma unroll
        for (int p = 0; p < 12; p++) {
            float4 pv = *(const float4*)&g_clsp[p][r][kc * 64 + c4];
            s.x += pv.x; s.y += pv.y; s.z += pv.z; s.w += pv.w;
        }
        cs[r][c4] = s.x; cs[r][c4 + 1] = s.y; cs[r][c4 + 2] = s.z; cs[r][c4 + 3] = s.w;
        float4 wv = *(const float4*)&proj_w[(size_t)(jc * 64 + r) * Cc + kc * 64 + c4];
        pw[r][c4] = wv.x; pw[r][c4 + 1] = wv.y; pw[r][c4 + 2] = wv.z; pw[r][c4 + 3] = wv.w;
    }
    __syncthreads();
    int ty = tid >> 4, tx = tid & 15;
    float acc[2][4] = {};
#pragma unroll 8
    for (int c = 0; c < 64; c++) {
        float a0 = cs[ty * 2 + 0][c], a1 = cs[ty * 2 + 1][c];
        float b0 = pw[tx * 4 + 0][c], b1 = pw[tx * 4 + 1][c];
        float b2 = pw[tx * 4 + 2][c], b3 = pw[tx * 4 + 3][c];
        acc[0][0] += a0 * b0; acc[0][1] += a0 * b1; acc[0][2] += a0 * b2; acc[0][3] += a0 * b3;
        acc[1][0] += a1 * b0; acc[1][1] += a1 * b1; acc[1][2] += a1 * b2; acc[1][3] += a1 * b3;
    }
#pragma unroll
    for (int i = 0; i < 2; i++) {
        float4 v = make_float4(acc[i][0], acc[i][1], acc[i][2], acc[i][3]);
        *(float4*)&g_outp[kc][ty * 2 + i][jc * 64 + tx * 4] = v;
    }
}

// ---------------- C3: combine proj partials + proj_b -> out[:,0,:] ----------------
__global__ void k_final(const float* __restrict__ proj_b, float* __restrict__ out) {
    int idx = blockIdx.x * 256 + threadIdx.x;
    if (idx >= Bb * Cc / 4) return;
    int b = idx / 192, j4 = (idx % 192) * 4;
    float4 s = *(const float4*)&proj_b[j4];
#pragma unroll
    for (int p = 0; p < 12; p++) {
        float4 pv = *(const float4*)&g_outp[p][b][j4];
        s.x += pv.x; s.y += pv.y; s.z += pv.z; s.w += pv.w;
    }
    *(float4*)&out[(size_t)b * Nt * Cc + j4] = s;
}

// ---------------- launch ----------------
extern "C" void kernel_launch(void* const* d_in, const int* in_sizes, int n_in,
                              void* d_out, int out_size) {
    (void)in_sizes; (void)n_in; (void)out_size;
    const float* x      = (const float*)d_in[0];
    const float* qkv_w  = (const float*)d_in[1];
    const float* qkv_b  = (const float*)d_in[2];
    const float* proj_w = (const float*)d_in[3];
    const float* proj_b = (const float*)d_in[4];
    float* out = (float*)d_out;

    cudaFuncSetAttribute(k_attn, cudaFuncAttributeMaxDynamicSharedMemorySize, SM_BYTES);

    k_qpart<<<dim3(12, 12), 512>>>(x, qkv_w);
    k_t    <<<dim3(12, 12), 512>>>(qkv_w, qkv_b);
    k_attn <<<dim3(64, SPLITS), 384, SM_BYTES>>>(x, out);
    k_cls  <<<dim3(12, 12), 512>>>(qkv_w);
    k_proj <<<dim3(12, 12), 512>>>(qkv_b, proj_w);
    k_final<<<48, 256>>>(proj_b, out);
}

// round 11
// speedup vs baseline: 1.0506x; 1.0506x over previous
#include <cuda_runtime.h>
#include <cstdint>
#include <cstddef>

// Problem constants
#define Bb 64
#define Nt 577
#define Cc 768
#define Hh 12
#define SCv 0.125f
#define SPLITS 9
#define CHUNK 66        // 9*66 = 594 >= 577, divisible by G -> branchless groups
#define G 6             // tokens per group in k_attn
#define NG (CHUNK / G)  // 11 full groups per CTA

// ---------------- scratch (device globals; no allocation) ----------------
__device__ __align__(16) float g_qpart[12][Bb][Cc];            // q partial sums (kc,b,j)
__device__ __align__(16) float g_t[Bb][Hh][Cc];                // SCALE * (q . Wk)
__device__ float            g_ob[Bb][Hh];                      // SCALE * (q . bk)
__device__ __align__(16) float g_pu[SPLITS][Bb][Hh][Cc];       // partial sum_n w*x
__device__ float            g_pd[SPLITS][Bb][Hh];              // partial sum_n w
__device__ __align__(16) float g_clsp[12][Bb][Cc];             // cls partials
__device__ __align__(16) float g_outp[12][Bb][Cc];             // proj partials

// ---------------- helpers ----------------
typedef unsigned long long ull;
__device__ __forceinline__ void fma2(ull &d, ull a, ull b) {
    asm("fma.rn.f32x2 %0, %1, %2, %0;" : "+l"(d) : "l"(a), "l"(b));
}
__device__ __forceinline__ float hadd2(ull a) {
    unsigned int lo, hi;
    asm("mov.b64 {%0,%1}, %2;" : "=r"(lo), "=r"(hi) : "l"(a));
    return __uint_as_float(lo) + __uint_as_float(hi);
}
__device__ __forceinline__ void cpa16(void* dst_smem, const void* src) {
    unsigned int d = (unsigned int)__cvta_generic_to_shared(dst_smem);
    asm volatile("cp.async.cg.shared.global [%0], [%1], 16;" :: "r"(d), "l"(src));
}

// ---------------- A1: q partials (k-split GEMM), 512 threads ----------------
__global__ void __launch_bounds__(512) k_qpart(const float* __restrict__ x,
                                               const float* __restrict__ qkv_w) {
    int jc = blockIdx.x, kc = blockIdx.y;
    __shared__ float xs[64][65];
    __shared__ float ws[64][65];
    int tid = threadIdx.x;
#pragma unroll
    for (int rr = 0; rr < 2; rr++) {
        int i = tid + rr * 512;
        int r = i >> 4, c4 = (i & 15) * 4;
        float4 xv = *(const float4*)&x[(size_t)r * Nt * Cc + kc * 64 + c4];
        xs[r][c4] = xv.x; xs[r][c4 + 1] = xv.y; xs[r][c4 + 2] = xv.z; xs[r][c4 + 3] = xv.w;
        float4 wv = *(const float4*)&qkv_w[(size_t)(jc * 64 + r) * Cc + kc * 64 + c4];
        ws[r][c4] = wv.x; ws[r][c4 + 1] = wv.y; ws[r][c4 + 2] = wv.z; ws[r][c4 + 3] = wv.w;
    }
    __syncthreads();
    int ty = tid >> 4, tx = tid & 15;     // 32 x 16
    float acc[2][4] = {};
#pragma unroll 8
    for (int d = 0; d < 64; d++) {
        float a0 = xs[ty * 2 + 0][d], a1 = xs[ty * 2 + 1][d];
        float b0 = ws[tx * 4 + 0][d], b1 = ws[tx * 4 + 1][d];
        float b2 = ws[tx * 4 + 2][d], b3 = ws[tx * 4 + 3][d];
        acc[0][0] += a0 * b0; acc[0][1] += a0 * b1; acc[0][2] += a0 * b2; acc[0][3] += a0 * b3;
        acc[1][0] += a1 * b0; acc[1][1] += a1 * b1; acc[1][2] += a1 * b2; acc[1][3] += a1 * b3;
    }
#pragma unroll
    for (int i = 0; i < 2; i++) {
        float4 v = make_float4(acc[i][0], acc[i][1], acc[i][2], acc[i][3]);
        *(float4*)&g_qpart[kc][ty * 2 + i][jc * 64 + tx * 4] = v;
    }
}

// ---------------- A2: t = SCALE*(q.Wk); ob  (q combined in-block), 512 thr ----------------
__global__ void __launch_bounds__(512) k_t(const float* __restrict__ qkv_w,
                                           const float* __restrict__ qkv_b) {
    int h = blockIdx.x, cc2 = blockIdx.y;
    __shared__ float qs[64][65];
    __shared__ float wk[64][65];
    int tid = threadIdx.x;
#pragma unroll
    for (int rr = 0; rr < 2; rr++) {
        int i = tid + rr * 512;
        int r = i >> 4, c4 = (i & 15) * 4;
        float4 s = *(const float4*)&qkv_b[h * 64 + c4];
#pragma unroll
        for (int kc = 0; kc < 12; kc++) {
            float4 p = *(const float4*)&g_qpart[kc][r][h * 64 + c4];
            s.x += p.x; s.y += p.y; s.z += p.z; s.w += p.w;
        }
        qs[r][c4] = s.x; qs[r][c4 + 1] = s.y; qs[r][c4 + 2] = s.z; qs[r][c4 + 3] = s.w;
        float4 wv = *(const float4*)&qkv_w[(size_t)(Cc + h * 64 + r) * Cc + cc2 * 64 + c4];
        wk[r][c4] = wv.x; wk[r][c4 + 1] = wv.y; wk[r][c4 + 2] = wv.z; wk[r][c4 + 3] = wv.w;
    }
    __syncthreads();
    int ty = tid >> 4, tx = tid & 15;
    float acc[2][4] = {};
#pragma unroll 8
    for (int d = 0; d < 64; d++) {
        float a0 = qs[ty * 2 + 0][d], a1 = qs[ty * 2 + 1][d];
        float b0 = wk[d][tx * 4 + 0], b1 = wk[d][tx * 4 + 1];
        float b2 = wk[d][tx * 4 + 2], b3 = wk[d][tx * 4 + 3];
        acc[0][0] += a0 * b0; acc[0][1] += a0 * b1; acc[0][2] += a0 * b2; acc[0][3] += a0 * b3;
        acc[1][0] += a1 * b0; acc[1][1] += a1 * b1; acc[1][2] += a1 * b2; acc[1][3] += a1 * b3;
    }
#pragma unroll
    for (int i = 0; i < 2; i++) {
        float4 v = make_float4(SCv * acc[i][0], SCv * acc[i][1], SCv * acc[i][2], SCv * acc[i][3]);
        *(float4*)&g_t[ty * 2 + i][h][cc2 * 64 + tx * 4] = v;
    }
    if (cc2 == 0 && tid < 64) {
        float ssum = 0.f;
#pragma unroll 8
        for (int d = 0; d < 64; d++) ssum += qs[tid][d] * qkv_b[Cc + h * 64 + d];
        g_ob[tid][h] = SCv * ssum;
    }
}

// ---------------- B: main fused streaming kernel (R8 skeleton, branchless bodies) ----------------
// grid (64 b, 9 split), 384 thr.  warp = 64-channel slice.
__global__ void __launch_bounds__(384, 2) k_attn(const float* __restrict__ x,
                                                 float* __restrict__ out) {
    int b = blockIdx.x, sp = blockIdx.y;
    int n0 = sp * CHUNK;
    int tid = threadIdx.x;
    int w = tid >> 5, l = tid & 31;
    int g3 = l >> 3;           // lane group 0..3 -> heads 3*g3..3*g3+2
    int q = l & 7;             // lane in group

    __shared__ __align__(16) float xb[2][G][Cc];
    __shared__ __align__(16) float pl[G][12][12];   // [token][warp][head]
    __shared__ __align__(16) float wsm[G][16];
    __shared__ float obs[12];
    __shared__ float dsm[G * 12];

    // phase-1 t: heads 3g3..3g3+2, channels w*64 + q*8 .. +7, packed
    int c1 = w * 64 + q * 8;
    ull t1[3][4];
#pragma unroll
    for (int i = 0; i < 3; i++) {
        ulonglong2 p0 = *(const ulonglong2*)&g_t[b][g3 * 3 + i][c1];
        ulonglong2 p1 = *(const ulonglong2*)&g_t[b][g3 * 3 + i][c1 + 4];
        t1[i][0] = p0.x; t1[i][1] = p0.y; t1[i][2] = p1.x; t1[i][3] = p1.y;
    }
    if (tid < 12) obs[tid] = g_ob[b][tid];

    // phase-2 accumulators: 2 channels per lane, all 12 heads
    int c2 = w * 64 + l * 2;
    float2 ua[12];
#pragma unroll
    for (int h = 0; h < 12; h++) ua[h] = make_float2(0.f, 0.f);
    float dp = 0.f;

    const float* xrow = x + (size_t)b * Nt * Cc;
    __syncthreads();

    // prologue: load group 0 (clamped)
#pragma unroll
    for (int r = 0; r < 3; r++) {
        int i = tid + r * 384;
        int j = i / 192, off = (i % 192) * 4;
        int n = n0 + j; int nsrc = n < Nt ? n : Nt - 1;
        cpa16(&xb[0][j][off], xrow + (size_t)nsrc * Cc + off);
    }
    asm volatile("cp.async.commit_group;");

    for (int gi = 0; gi < NG; gi++) {
        int buf = gi & 1;
        int nbase = n0 + gi * G;
        // prefetch next group (clamped; last iteration commits empty group)
        if (gi + 1 < NG) {
            int nb2 = nbase + G;
#pragma unroll
            for (int r = 0; r < 3; r++) {
                int i = tid + r * 384;
                int j = i / 192, off = (i % 192) * 4;
                int n = nb2 + j; int nsrc = n < Nt ? n : Nt - 1;
                cpa16(&xb[buf ^ 1][j][off], xrow + (size_t)nsrc * Cc + off);
            }
        }
        asm volatile("cp.async.commit_group;");
        asm volatile("cp.async.wait_group 1;");
        __syncthreads();

        // ---- phase 1: logits (branchless, 6 tokens interleave) ----
#pragma unroll
        for (int j = 0; j < G; j++) {
            ulonglong2 xp0 = *(const ulonglong2*)&xb[buf][j][c1];
            ulonglong2 xp1 = *(const ulonglong2*)&xb[buf][j][c1 + 4];
            ull xv0 = xp0.x, xv1 = xp0.y, xv2 = xp1.x, xv3 = xp1.y;
            float s[3];
#pragma unroll
            for (int i = 0; i < 3; i++) {
                ull a = 0ull;
                fma2(a, xv0, t1[i][0]); fma2(a, xv1, t1[i][1]);
                fma2(a, xv2, t1[i][2]); fma2(a, xv3, t1[i][3]);
                float sv = hadd2(a);
                sv += __shfl_xor_sync(0xffffffffu, sv, 4, 8);
                sv += __shfl_xor_sync(0xffffffffu, sv, 2, 8);
                sv += __shfl_xor_sync(0xffffffffu, sv, 1, 8);
                s[i] = sv;
            }
            if (q < 3) pl[j][w][g3 * 3 + q] = s[q];
        }
        __syncthreads();

        // ---- combine: 72 threads -> weights (0 for pad tokens) ----
        if (tid < G * 12) {
            int gg = tid / 12, h = tid % 12;
            int n = nbase + gg;
            float s = 0.f;
#pragma unroll
            for (int ww = 0; ww < 12; ww++) s += pl[gg][ww][h];
            float wv = (n < Nt) ? __expf(s + obs[h]) : 0.f;
            dp += wv;
            wsm[gg][h] = wv;
        }
        __syncthreads();

        // ---- phase 2: accumulate (branchless) + guarded copy out ----
#pragma unroll
        for (int j = 0; j < G; j++) {
            int n = nbase + j;
            float4 wA = *(const float4*)&wsm[j][0];
            float4 wB = *(const float4*)&wsm[j][4];
            float4 wC = *(const float4*)&wsm[j][8];
            float2 xv = *(const float2*)&xb[buf][j][c2];
            ua[0].x = fmaf(wA.x, xv.x, ua[0].x);  ua[0].y = fmaf(wA.x, xv.y, ua[0].y);
            ua[1].x = fmaf(wA.y, xv.x, ua[1].x);  ua[1].y = fmaf(wA.y, xv.y, ua[1].y);
            ua[2].x = fmaf(wA.z, xv.x, ua[2].x);  ua[2].y = fmaf(wA.z, xv.y, ua[2].y);
            ua[3].x = fmaf(wA.w, xv.x, ua[3].x);  ua[3].y = fmaf(wA.w, xv.y, ua[3].y);
            ua[4].x = fmaf(wB.x, xv.x, ua[4].x);  ua[4].y = fmaf(wB.x, xv.y, ua[4].y);
            ua[5].x = fmaf(wB.y, xv.x, ua[5].x);  ua[5].y = fmaf(wB.y, xv.y, ua[5].y);
            ua[6].x = fmaf(wB.z, xv.x, ua[6].x);  ua[6].y = fmaf(wB.z, xv.y, ua[6].y);
            ua[7].x = fmaf(wB.w, xv.x, ua[7].x);  ua[7].y = fmaf(wB.w, xv.y, ua[7].y);
            ua[8].x = fmaf(wC.x, xv.x, ua[8].x);  ua[8].y = fmaf(wC.x, xv.y, ua[8].y);
            ua[9].x = fmaf(wC.y, xv.x, ua[9].x);  ua[9].y = fmaf(wC.y, xv.y, ua[9].y);
            ua[10].x = fmaf(wC.z, xv.x, ua[10].x); ua[10].y = fmaf(wC.z, xv.y, ua[10].y);
            ua[11].x = fmaf(wC.w, xv.x, ua[11].x); ua[11].y = fmaf(wC.w, xv.y, ua[11].y);
            if (n > 0 && n < Nt)
                *(float2*)&out[((size_t)b * Nt + n) * Cc + c2] = xv;
        }
        __syncthreads();
    }

    // store split partials
#pragma unroll
    for (int h = 0; h < 12; h++)
        *(float2*)&g_pu[sp][b][h][c2] = ua[h];
    if (tid < G * 12) dsm[tid] = dp;
    __syncthreads();
    if (tid < 12) {
        float s = 0.f;
#pragma unroll
        for (int gg = 0; gg < G; gg++) s += dsm[gg * 12 + tid];
        g_pd[sp][b][tid] = s;
    }
}

// ---------------- C1: cls partials (fused split-combine + normalize), 512 thr ----------------
__global__ void __launch_bounds__(512) k_cls(const float* __restrict__ qkv_w) {
    int h = blockIdx.x, kc = blockIdx.y;
    __shared__ float us[64][65];
    __shared__ float wv[64][65];
    __shared__ float dsh[64];
    int tid = threadIdx.x;
    if (tid < 64) {
        float s = 0.f;
#pragma unroll
        for (int sp = 0; sp < SPLITS; sp++) s += g_pd[sp][tid][h];
        dsh[tid] = 1.f / s;
    }
    __syncthreads();
#pragma unroll
    for (int rr = 0; rr < 2; rr++) {
        int i = tid + rr * 512;
        int r = i >> 4, c4 = (i & 15) * 4;
        float4 acc = make_float4(0.f, 0.f, 0.f, 0.f);
#pragma unroll
        for (int sp = 0; sp < SPLITS; sp++) {
            float4 p = *(const float4*)&g_pu[sp][r][h][kc * 64 + c4];
            acc.x += p.x; acc.y += p.y; acc.z += p.z; acc.w += p.w;
        }
        float inv = dsh[r];
        us[r][c4] = acc.x * inv; us[r][c4 + 1] = acc.y * inv;
        us[r][c4 + 2] = acc.z * inv; us[r][c4 + 3] = acc.w * inv;
        float4 wvv = *(const float4*)&qkv_w[(size_t)(2 * Cc + h * 64 + r) * Cc + kc * 64 + c4];
        wv[r][c4] = wvv.x; wv[r][c4 + 1] = wvv.y; wv[r][c4 + 2] = wvv.z; wv[r][c4 + 3] = wvv.w;
    }
    __syncthreads();
    int ty = tid >> 4, tx = tid & 15;
    float acc[2][4] = {};
#pragma unroll 8
    for (int c = 0; c < 64; c++) {
        float a0 = us[ty * 2 + 0][c], a1 = us[ty * 2 + 1][c];
        float b0 = wv[tx * 4 + 0][c], b1 = wv[tx * 4 + 1][c];
        float b2 = wv[tx * 4 + 2][c], b3 = wv[tx * 4 + 3][c];
        acc[0][0] += a0 * b0; acc[0][1] += a0 * b1; acc[0][2] += a0 * b2; acc[0][3] += a0 * b3;
        acc[1][0] += a1 * b0; acc[1][1] += a1 * b1; acc[1][2] += a1 * b2; acc[1][3] += a1 * b3;
    }
#pragma unroll
    for (int i = 0; i < 2; i++) {
        float4 v = make_float4(acc[i][0], acc[i][1], acc[i][2], acc[i][3]);
        *(float4*)&g_clsp[kc][ty * 2 + i][h * 64 + tx * 4] = v;
    }
}

// ---------------- C2: proj partials, 512 thr ----------------
__global__ void __launch_bounds__(512) k_proj(const float* __restrict__ qkv_b,
                                              const float* __restrict__ proj_w) {
    int jc = blockIdx.x, kc = blockIdx.y;
    __shared__ float cs[64][65];
    __shared__ float pw[64][65];
    int tid = threadIdx.x;
#pragma unroll
    for (int rr = 0; rr < 2; rr++) {
        int i = tid + rr * 512;
        int r = i >> 4, c4 = (i & 15) * 4;
        float4 s = *(const float4*)&qkv_b[2 * Cc + kc * 64 + c4];
#pragma unroll
        for (int p = 0; p < 12; p++) {
            float4 pv = *(const float4*)&g_clsp[p][r][kc * 64 + c4];
            s.x += pv.x; s.y += pv.y; s.z += pv.z; s.w += pv.w;
        }
        cs[r][c4] = s.x; cs[r][c4 + 1] = s.y; cs[r][c4 + 2] = s.z; cs[r][c4 + 3] = s.w;
        float4 wv = *(const float4*)&proj_w[(size_t)(jc * 64 + r) * Cc + kc * 64 + c4];
        pw[r][c4] = wv.x; pw[r][c4 + 1] = wv.y; pw[r][c4 + 2] = wv.z; pw[r][c4 + 3] = wv.w;
    }
    __syncthreads();
    int ty = tid >> 4, tx = tid & 15;
    float acc[2][4] = {};
#pragma unroll 8
    for (int c = 0; c < 64; c++) {
        float a0 = cs[ty * 2 + 0][c], a1 = cs[ty * 2 + 1][c];
        float b0 = pw[tx * 4 + 0][c], b1 = pw[tx * 4 + 1][c];
        float b2 = pw[tx * 4 + 2][c], b3 = pw[tx * 4 + 3][c];
        acc[0][0] += a0 * b0; acc[0][1] += a0 * b1; acc[0][2] += a0 * b2; acc[0][3] += a0 * b3;
        acc[1][0] += a1 * b0; acc[1][1] += a1 * b1; acc[1][2] += a1 * b2; acc[1][3] += a1 * b3;
    }
#pragma unroll
    for (int i = 0; i < 2; i++) {
        float4 v = make_float4(acc[i][0], acc[i][1], acc[i][2], acc[i][3]);
        *(float4*)&g_outp[kc][ty * 2 + i][jc * 64 + tx * 4] = v;
    }
}

// ---------------- C3: combine proj partials + proj_b -> out[:,0,:] ----------------
__global__ void k_final(const float* __restrict__ proj_b, float* __restrict__ out) {
    int idx = blockIdx.x * 256 + threadIdx.x;
    if (idx >= Bb * Cc / 4) return;
    int b = idx / 192, j4 = (idx % 192) * 4;
    float4 s = *(const float4*)&proj_b[j4];
#pragma unroll
    for (int p = 0; p < 12; p++) {
        float4 pv = *(const float4*)&g_outp[p][b][j4];
        s.x += pv.x; s.y += pv.y; s.z += pv.z; s.w += pv.w;
    }
    *(float4*)&out[(size_t)b * Nt * Cc + j4] = s;
}

// ---------------- launch ----------------
extern "C" void kernel_launch(void* const* d_in, const int* in_sizes, int n_in,
                              void* d_out, int out_size) {
    (void)in_sizes; (void)n_in; (void)out_size;
    const float* x      = (const float*)d_in[0];
    const float* qkv_w  = (const float*)d_in[1];
    const float* qkv_b  = (const float*)d_in[2];
    const float* proj_w = (const float*)d_in[3];
    const float* proj_b = (const float*)d_in[4];
    float* out = (float*)d_out;

    k_qpart<<<dim3(12, 12), 512>>>(x, qkv_w);
    k_t    <<<dim3(12, 12), 512>>>(qkv_w, qkv_b);
    k_attn <<<dim3(64, SPLITS), 384>>>(x, out);
    k_cls  <<<dim3(12, 12), 512>>>(qkv_w);
    k_proj <<<dim3(12, 12), 512>>>(qkv_b, proj_w);
    k_final<<<48, 256>>>(proj_b, out);
}